// round 6
// baseline (speedup 1.0000x reference)
#include <cuda_runtime.h>
#include <cstdint>
#include <cstddef>

// out[t, n*16+f] = relu(bias[f] + sum_{j=0..31} x[t-2j-1, n] * w_pn[j][f])
// w_pn = per-filter l2-normalized relu(weights); rows t-2j-1 < 0 contribute 0.
//
// Block: 32 n x 32 t x 16 f (256 thr, 8 warps). x staged transposed in smem
// (96-row strip, row stride 98 floats -> 49 ull, gcd(49,16)=1 -> conflict-free
// LDS.64 across lanes). Thread: 1 n x 16 t x 4 f with t-PACKED f32x2 accs.
// j-loop: outer x4 (#pragma unroll 1) x inner 8 (unrolled). Weights double-
// buffered in registers (step i prefetches step i+1), x window refilled
// mid-step -> all LDS latencies covered by >=1 full step of distance.

#define T_DIM 2048
#define N_DIM 4096
#define L_DIM 32
#define F_DIM 16
#define OUTW  (N_DIM * F_DIM)

#define RSTRIDE   98   // floats per staged row
#define RSTRIDE_U 49   // ull per staged row

// manual smem layout (ull units): weights[528] | biases[16] | sx
#define SW_ULL   528                   // 512 weights + 16 pad (dead OOB reads)
#define SB_ULL   16
#define SX_OFF_B ((SW_ULL + SB_ULL) * 8)
#define SMEM_BYTES (SX_OFF_B + 32 * RSTRIDE * 4)

using ull = unsigned long long;

__device__ __forceinline__ ull dup2(float v) {
    ull r;
    unsigned u = __float_as_uint(v);
    asm("mov.b64 %0, {%1, %1};" : "=l"(r) : "r"(u));
    return r;
}

__device__ __forceinline__ void fma2(ull& d, ull a, ull b) {
    asm("fma.rn.f32x2 %0, %1, %2, %0;" : "+l"(d) : "l"(a), "l"(b));
}

__device__ __forceinline__ float2 unpack2(ull v) {
    float2 r;
    asm("mov.b64 {%0, %1}, %2;" : "=f"(r.x), "=f"(r.y) : "l"(v));
    return r;
}

__global__ void __launch_bounds__(256, 2)
tlayer_kernel(const float* __restrict__ x,
              const float* __restrict__ Wg,
              const float* __restrict__ Bg,
              float* __restrict__ out)
{
    __shared__ __align__(16) char smem_raw[SMEM_BYTES];
    ull*   swdup = reinterpret_cast<ull*>(smem_raw);            // {w,w} per (j,f)
    ull*   sbdup = swdup + SW_ULL;                              // {b,b} per f
    float* sx    = reinterpret_cast<float*>(smem_raw + SX_OFF_B);

    const int tid  = threadIdx.x;
    const int lane = tid & 31;
    const int warp = tid >> 5;

    const int n0    = blockIdx.x * 32;
    const int t0    = blockIdx.y * 32;
    const int tbase = t0 - 63;

    // ---- weight prep: relu + per-filter l2 normalize, stored duplicated ----
    if (tid < F_DIM) {
        float ss = 0.0f;
        for (int j = 0; j < L_DIM; ++j) {
            float wv = fmaxf(__ldg(Wg + j * F_DIM + tid), 0.0f);
            ss += wv * wv;
        }
        float inv = rsqrtf(fmaxf(ss, 1e-12f));
        for (int j = 0; j < L_DIM; ++j) {
            float wn = fmaxf(__ldg(Wg + j * F_DIM + tid), 0.0f) * inv;
            swdup[j * F_DIM + tid] = dup2(wn);
        }
        sbdup[tid] = dup2(__ldg(Bg + tid));
    }

    // ---- stage x transposed: sx[lane][i] = x[tbase+i][n0+lane], 96 rows ----
#pragma unroll
    for (int k = 0; k < 12; ++k) {
        int i = warp + k * 8;
        int g = tbase + i;
        float v = 0.0f;
        if (g >= 0 && g < T_DIM) v = __ldg(x + (size_t)g * N_DIM + n0 + lane);
        sx[lane * RSTRIDE + i] = v;
    }
    __syncthreads();

    // ---- compute: warp -> (tg: 16 t, fg: 4 f) ----
    const int tg = warp >> 2;
    const int fg = warp & 3;

    const ull* xr = reinterpret_cast<const ull*>(sx) + lane * RSTRIDE_U
                    + (tg * 8 + 31);                 // xr[p - j] = x pair
    const ull* wp = swdup + fg * 4;                  // row stride 16 ull

    ull acc[8][4];
#pragma unroll
    for (int ff = 0; ff < 4; ++ff) {
        ull b = sbdup[fg * 4 + ff];
#pragma unroll
        for (int p = 0; p < 8; ++p) acc[p][ff] = b;
    }

    // x window: at start of outer o, W[m] = xr[m - 8o]
    ull W[8];
#pragma unroll
    for (int m = 0; m < 8; ++m) W[m] = xr[m];

    // weight double buffer: wbuf[phase][4]; phase = j & 1
    ull wbuf[2][4];
#pragma unroll
    for (int k = 0; k < 4; ++k) wbuf[0][k] = wp[k];  // j = 0

#pragma unroll 1
    for (int o = 0; o < 4; ++o) {
        const ull* wrow = wp + o * (8 * F_DIM);      // weights row for j = 8o
        const ull* xrw  = xr - o * 8;
#pragma unroll
        for (int i = 0; i < 8; ++i) {
            const int cur = i & 1;
            const int nxt = cur ^ 1;
            // prefetch next step's weights (dead smem-pad read at j=31)
#pragma unroll
            for (int k = 0; k < 4; ++k) wbuf[nxt][k] = wrow[(i + 1) * F_DIM + k];

            // p = 7 first: frees window slot (7-i) for the refill below
            {
                ull xv = W[(7 - i) & 7];
                fma2(acc[7][0], xv, wbuf[cur][0]);
                fma2(acc[7][1], xv, wbuf[cur][1]);
                fma2(acc[7][2], xv, wbuf[cur][2]);
                fma2(acc[7][3], xv, wbuf[cur][3]);
            }
            // refill: slot (7-i) <- xrw[-(i+1)], first used early next step
            W[(7 - i) & 7] = xrw[-(i + 1)];

#pragma unroll
            for (int p = 6; p >= 0; --p) {
                ull xv = W[(p - i + 8) & 7];
                fma2(acc[p][0], xv, wbuf[cur][0]);
                fma2(acc[p][1], xv, wbuf[cur][1]);
                fma2(acc[p][2], xv, wbuf[cur][2]);
                fma2(acc[p][3], xv, wbuf[cur][3]);
            }
        }
    }

    // ---- epilogue: relu + f-contiguous float4 stores ----
    const size_t col = (size_t)(n0 + lane) * F_DIM + fg * 4;
#pragma unroll
    for (int p = 0; p < 8; ++p) {
        int t = t0 + tg * 16 + 2 * p;
        float2 a0 = unpack2(acc[p][0]);
        float2 a1 = unpack2(acc[p][1]);
        float2 a2 = unpack2(acc[p][2]);
        float2 a3 = unpack2(acc[p][3]);
        float4 v0, v1;
        v0.x = fmaxf(a0.x, 0.0f); v0.y = fmaxf(a1.x, 0.0f);
        v0.z = fmaxf(a2.x, 0.0f); v0.w = fmaxf(a3.x, 0.0f);
        v1.x = fmaxf(a0.y, 0.0f); v1.y = fmaxf(a1.y, 0.0f);
        v1.z = fmaxf(a2.y, 0.0f); v1.w = fmaxf(a3.y, 0.0f);
        *reinterpret_cast<float4*>(out + (size_t)t * OUTW + col)       = v0;
        *reinterpret_cast<float4*>(out + (size_t)(t + 1) * OUTW + col) = v1;
    }
}

extern "C" void kernel_launch(void* const* d_in, const int* in_sizes, int n_in,
                              void* d_out, int out_size) {
    (void)in_sizes; (void)n_in; (void)out_size;
    const float* x = (const float*)d_in[0];   // [2048, 4096]
    const float* W = (const float*)d_in[1];   // [32, 16]
    const float* B = (const float*)d_in[2];   // [16]
    float* out = (float*)d_out;               // [2048, 65536]

    dim3 grid(N_DIM / 32, T_DIM / 32);        // (128, 64)
    tlayer_kernel<<<grid, 256>>>(x, W, B, out);
}

// round 8
// speedup vs baseline: 1.2825x; 1.2825x over previous
#include <cuda_runtime.h>
#include <cstdint>
#include <cstddef>

// out[t, n*16+f] = relu(bias[f] + sum_{j=0..31} x[t-2j-1, n] * w_pn[j][f])
// w_pn = per-filter l2-normalized relu(weights); rows t-2j-1 < 0 contribute 0.
//
// R3 structure (best: 216us) + two targeted fixes:
//  - lag loop in 8 groups of 4; each group batch-prefetches the NEXT group's
//    8 x rows (MLP=8, distance ~4 j-steps) -> hides DRAM/L2 latency that was
//    exposed behind the 512MB store stream.
//  - __stcs streaming stores -> output stream evicts first, x stays in L2.
// Thread tile: 1 n x 4 t x 16 f, f-paired f32x2 accumulators, dup2'd x operand.

#define T_DIM 2048
#define N_DIM 4096
#define L_DIM 32
#define F_DIM 16
#define OUTW  (N_DIM * F_DIM)

using ull = unsigned long long;

__device__ __forceinline__ ull dup2(float v) {
    ull r;
    unsigned u = __float_as_uint(v);
    asm("mov.b64 %0, {%1, %1};" : "=l"(r) : "r"(u));
    return r;
}

__device__ __forceinline__ void fma2(ull& d, ull a, ull b) {
    asm("fma.rn.f32x2 %0, %1, %2, %0;" : "+l"(d) : "l"(a), "l"(b));
}

__device__ __forceinline__ float2 unpack2(ull v) {
    float2 r;
    asm("mov.b64 {%0, %1}, %2;" : "=f"(r.x), "=f"(r.y) : "l"(v));
    return r;
}

// Load x[t0 + off, n] where p = xn + t0*N and off is a compile-time literal:
// the address folds to [base + imm], no per-load ALU.
template<bool GUARD>
__device__ __forceinline__ float ldrow(const float* __restrict__ p, int t0, int off) {
    if (GUARD && (t0 + off < 0)) return 0.0f;
    return __ldg(p + (ptrdiff_t)off * N_DIM);
}

template<bool GUARD>
__device__ __forceinline__ void compute_tile(
    const float* __restrict__ xt,     // xn + t0*N  (base row pointer)
    float* __restrict__ op,           // out + t0*OUTW + n*16
    const ull* __restrict__ sw8,      // smem weights as f32x2 pairs [32][8]
    const ull* __restrict__ sb2,      // smem biases  as f32x2 pairs [8]
    int t0)
{
    // acc[tt][p] = {out[t0+tt, 2p], out[t0+tt, 2p+1]} pre-relu
    ull acc[4][8];
#pragma unroll
    for (int p = 0; p < 8; ++p) {
        ull b = sb2[p];
        acc[0][p] = b; acc[1][p] = b; acc[2][p] = b; acc[3][p] = b;
    }

    // Window invariant entering group g (j0 = 4g): win[k] = x[t0 - 2*j0 - 7 + k],
    // k = 0..9. Lag j = j0+d needs rows t0-2j-1+i = win[6-2d+i], i = 0..3.
    float win[10];
#pragma unroll
    for (int k = 0; k < 10; ++k)
        win[k] = ldrow<GUARD>(xt, t0, -7 + k);

#pragma unroll
    for (int g = 0; g < 8; ++g) {
        // Batch-prefetch next group's 8 rows: x[t0 - 8g - 15 + k], k = 0..7.
        // Independent LDGs (MLP=8), consumed one full group (~4 j-steps) later.
        float nbuf[8];
        if (g < 7) {
#pragma unroll
            for (int k = 0; k < 8; ++k)
                nbuf[k] = ldrow<GUARD>(xt, t0, -8 * g - 15 + k);
        }

#pragma unroll
        for (int d = 0; d < 4; ++d) {
            const int j = 4 * g + d;
            ull x0 = dup2(win[6 - 2 * d + 0]);
            ull x1 = dup2(win[6 - 2 * d + 1]);
            ull x2 = dup2(win[6 - 2 * d + 2]);
            ull x3 = dup2(win[6 - 2 * d + 3]);
#pragma unroll
            for (int p = 0; p < 8; ++p) {
                ull wj = sw8[j * 8 + p];     // broadcast LDS.64, reused 4x
                fma2(acc[0][p], x0, wj);
                fma2(acc[1][p], x1, wj);
                fma2(acc[2][p], x2, wj);
                fma2(acc[3][p], x3, wj);
            }
        }

        // Shift window: win'[8]=win[0], win'[9]=win[1], win'[0..7]=nbuf.
        if (g < 7) {
            float c0 = win[0], c1 = win[1];
            win[8] = c0; win[9] = c1;
#pragma unroll
            for (int k = 0; k < 8; ++k) win[k] = nbuf[k];
        }
    }

    // relu + streaming store: 16 contiguous floats per t -> 4x STG.128 each;
    // warp lanes are consecutive n -> contiguous 2KB rows. .cs keeps x in L2.
#pragma unroll
    for (int tt = 0; tt < 4; ++tt) {
        float4* dst = reinterpret_cast<float4*>(op + (size_t)tt * OUTW);
#pragma unroll
        for (int q = 0; q < 4; ++q) {
            float2 a = unpack2(acc[tt][2 * q]);
            float2 b = unpack2(acc[tt][2 * q + 1]);
            float4 v;
            v.x = fmaxf(a.x, 0.0f);
            v.y = fmaxf(a.y, 0.0f);
            v.z = fmaxf(b.x, 0.0f);
            v.w = fmaxf(b.y, 0.0f);
            __stcs(dst + q, v);
        }
    }
}

__global__ void __launch_bounds__(128)
tlayer_kernel(const float* __restrict__ x,
              const float* __restrict__ W,
              const float* __restrict__ B,
              float* __restrict__ out)
{
    __shared__ __align__(8) float sw[L_DIM * F_DIM];  // normalized weights [j][f]
    __shared__ __align__(8) float sb[F_DIM];

    const int tid = threadIdx.x;

    // Per-block weight prep: relu + per-filter l2 normalize (matches reference).
    if (tid < F_DIM) {
        float ss = 0.0f;
        for (int j = 0; j < L_DIM; ++j) {
            float wv = fmaxf(__ldg(W + j * F_DIM + tid), 0.0f);
            ss += wv * wv;
        }
        float inv = rsqrtf(fmaxf(ss, 1e-12f));
        for (int j = 0; j < L_DIM; ++j) {
            sw[j * F_DIM + tid] = fmaxf(__ldg(W + j * F_DIM + tid), 0.0f) * inv;
        }
        sb[tid] = __ldg(B + tid);
    }
    __syncthreads();

    const int lane = tid & 31;
    const int warp = tid >> 5;

    const int n  = blockIdx.x * 32 + lane;        // 128 n-blocks
    const int t0 = blockIdx.y * 16 + warp * 4;    // 128 t-blocks, 4 warps x 4 t

    const float* xt = x + (size_t)t0 * N_DIM + n;
    float*       op = out + (size_t)t0 * OUTW + (size_t)n * F_DIM;
    const ull*   sw8 = reinterpret_cast<const ull*>(sw);
    const ull*   sb2 = reinterpret_cast<const ull*>(sb);

    // Deepest row touched is t0 - 63; guard only the first t-blocks.
    if (t0 >= 63) {
        compute_tile<false>(xt, op, sw8, sb2, t0);
    } else {
        compute_tile<true>(xt, op, sw8, sb2, t0);
    }
}

extern "C" void kernel_launch(void* const* d_in, const int* in_sizes, int n_in,
                              void* d_out, int out_size) {
    (void)in_sizes; (void)n_in; (void)out_size;
    const float* x = (const float*)d_in[0];   // [2048, 4096]
    const float* W = (const float*)d_in[1];   // [32, 16]
    const float* B = (const float*)d_in[2];   // [16]
    float* out = (float*)d_out;               // [2048, 65536]

    dim3 grid(N_DIM / 32, T_DIM / 16);        // (128, 128)
    tlayer_kernel<<<grid, 128>>>(x, W, B, out);
}